// round 2
// baseline (speedup 1.0000x reference)
#include <cuda_runtime.h>
#include <cuda_bf16.h>
#include <math.h>

// Shapes (fixed): B=2, T=512, D=256, H=8, c=32
#define NTOK 1024
#define DM   256
#define NH   8
#define HC   32
#define T    512

__device__ float g_qkv[NTOK * 3 * DM];
__device__ float g_x1 [NTOK * DM];
__device__ float g_h  [NTOK * 4 * DM];

__device__ __forceinline__ unsigned f2tf32(float f) {
    unsigned u;
    asm("cvt.rna.tf32.f32 %0, %1;" : "=r"(u) : "f"(f));
    return u;
}

// ---------------------------------------------------------------------------
// TF32 tensor-core GEMM: C[M,N] = act(A @ B + bias) (+ res)
// BM=BN=64, BK=16, 256 threads = 8 warps (2x4 warp grid, warp tile 32x16).
// mma.sync.aligned.m16n8k8.row.col.f32.tf32.tf32.f32
// smem staged operands are pre-rounded to tf32 (cvt.rna) at store time.
// ---------------------------------------------------------------------------
template<int ACT, bool RES>
__global__ void gemm_tc(const float* __restrict__ A, const float* __restrict__ B,
                        const float* __restrict__ bias, const float* __restrict__ res,
                        float* __restrict__ C, int M, int N, int K)
{
    __shared__ float As[64 * 17];   // row stride 17
    __shared__ float Bs[16 * 68];   // row stride 68 (16B-aligned rows)

    const int tid  = threadIdx.x;
    const int w    = tid >> 5;
    const int lane = tid & 31;
    const int g    = lane >> 2;     // group 0..7
    const int tg   = lane & 3;      // thread-in-group 0..3
    const int warpM = w >> 2;       // 0..1
    const int warpN = w & 3;        // 0..3

    const int row0 = blockIdx.y * 64;
    const int col0 = blockIdx.x * 64;

    // global->smem load mapping (same as fp32 version)
    const int ar = tid >> 2;            // 0..63
    const int ak = (tid & 3) << 2;      // 0,4,8,12
    const int br = tid >> 4;            // 0..15
    const int bc = (tid & 15) << 2;     // 0..60

    float acc[2][2][4] = {};

    for (int k0 = 0; k0 < K; k0 += 16) {
        float4 av = *(const float4*)(A + (size_t)(row0 + ar) * K + k0 + ak);
        As[ar * 17 + ak + 0] = __uint_as_float(f2tf32(av.x));
        As[ar * 17 + ak + 1] = __uint_as_float(f2tf32(av.y));
        As[ar * 17 + ak + 2] = __uint_as_float(f2tf32(av.z));
        As[ar * 17 + ak + 3] = __uint_as_float(f2tf32(av.w));

        float4 bv = *(const float4*)(B + (size_t)(k0 + br) * N + col0 + bc);
        Bs[br * 68 + bc + 0] = __uint_as_float(f2tf32(bv.x));
        Bs[br * 68 + bc + 1] = __uint_as_float(f2tf32(bv.y));
        Bs[br * 68 + bc + 2] = __uint_as_float(f2tf32(bv.z));
        Bs[br * 68 + bc + 3] = __uint_as_float(f2tf32(bv.w));

        __syncthreads();

        #pragma unroll
        for (int ks = 0; ks < 2; ks++) {
            const int kk = ks * 8;
            unsigned a[2][4], b[2][2];
            #pragma unroll
            for (int i = 0; i < 2; i++) {
                const int rb = warpM * 32 + i * 16;
                a[i][0] = __float_as_uint(As[(rb + g    ) * 17 + kk + tg    ]);
                a[i][1] = __float_as_uint(As[(rb + g + 8) * 17 + kk + tg    ]);
                a[i][2] = __float_as_uint(As[(rb + g    ) * 17 + kk + tg + 4]);
                a[i][3] = __float_as_uint(As[(rb + g + 8) * 17 + kk + tg + 4]);
            }
            #pragma unroll
            for (int j = 0; j < 2; j++) {
                const int cb = warpN * 16 + j * 8;
                b[j][0] = __float_as_uint(Bs[(kk + tg    ) * 68 + cb + g]);
                b[j][1] = __float_as_uint(Bs[(kk + tg + 4) * 68 + cb + g]);
            }
            #pragma unroll
            for (int i = 0; i < 2; i++)
                #pragma unroll
                for (int j = 0; j < 2; j++) {
                    asm volatile(
                        "mma.sync.aligned.m16n8k8.row.col.f32.tf32.tf32.f32 "
                        "{%0,%1,%2,%3}, {%4,%5,%6,%7}, {%8,%9}, {%0,%1,%2,%3};"
                        : "+f"(acc[i][j][0]), "+f"(acc[i][j][1]),
                          "+f"(acc[i][j][2]), "+f"(acc[i][j][3])
                        : "r"(a[i][0]), "r"(a[i][1]), "r"(a[i][2]), "r"(a[i][3]),
                          "r"(b[j][0]), "r"(b[j][1]));
                }
        }
        __syncthreads();
    }

    // epilogue
    #pragma unroll
    for (int i = 0; i < 2; i++) {
        const int rb = row0 + warpM * 32 + i * 16;
        #pragma unroll
        for (int j = 0; j < 2; j++) {
            const int cb = col0 + warpN * 16 + j * 8;
            #pragma unroll
            for (int rg = 0; rg < 2; rg++) {
                const int r = rb + g + rg * 8;
                #pragma unroll
                for (int cg = 0; cg < 2; cg++) {
                    const int c = cb + tg * 2 + cg;
                    float v = acc[i][j][rg * 2 + cg] + bias[c];
                    if (ACT == 1)
                        v = v * __fdividef(1.f, 1.f + __expf(-1.702f * v));
                    if (RES) v += res[(size_t)r * N + c];
                    C[(size_t)r * N + c] = v;
                }
            }
        }
    }
}

// ---------------------------------------------------------------------------
// L1-distance attention + residual (unchanged from R1)
// ---------------------------------------------------------------------------
__global__ void attn_kernel(const float* __restrict__ x, const float* __restrict__ qkv,
                            float* __restrict__ x1)
{
    extern __shared__ float sh[];
    float* Ksh = sh;
    float* Vsh = sh + 16384;

    const int bid = blockIdx.x;
    const int bh  = bid >> 3;
    const int qb  = bid & 7;
    const int b   = bh >> 3;
    const int hh  = bh & 7;
    const int tid = threadIdx.x;
    const int w   = tid >> 5;
    const int lane = tid & 31;
    const int t0  = qb * 64;

    const float* qkv_bh = qkv + (size_t)b * T * 768 + hh * 96;

    for (int i = tid; i < T * 8; i += 256) {
        int s = i >> 3, j = i & 7;
        ((float4*)Ksh)[i] = ((const float4*)(qkv_bh + (size_t)s * 768 + 32))[j];
        ((float4*)Vsh)[i] = ((const float4*)(qkv_bh + (size_t)s * 768 + 64))[j];
    }

    const int qg   = w & 1;
    const int ss   = w >> 1;
    const int qidx = qg * 32 + lane;
    const int t    = t0 + qidx;

    float4 q4[8];
    {
        const float4* qsrc = (const float4*)(qkv_bh + (size_t)t * 768);
        #pragma unroll
        for (int j = 0; j < 8; j++) q4[j] = qsrc[j];
    }
    __syncthreads();

    const float scale = 0.1767766952966369f;
    float m = 0.f, l = 0.f;
    float4 o4[8];
    #pragma unroll
    for (int j = 0; j < 8; j++) o4[j] = make_float4(0.f, 0.f, 0.f, 0.f);

    const int s_begin = ss * 128;
    for (int s = s_begin; s < s_begin + 128; s++) {
        const float4* krow = (const float4*)(Ksh + s * 32);
        float dist = 0.f;
        #pragma unroll
        for (int j = 0; j < 8; j++) {
            float4 kv = krow[j];
            dist += fabsf(q4[j].x - kv.x) + fabsf(q4[j].y - kv.y)
                  + fabsf(q4[j].z - kv.z) + fabsf(q4[j].w - kv.w);
        }
        float wgt = (s == t) ? 0.f : __fdividef(1.f, 0.001f + dist * scale);
        if (wgt > m) {
            float corr = __expf(m - wgt);
            l *= corr;
            #pragma unroll
            for (int j = 0; j < 8; j++) {
                o4[j].x *= corr; o4[j].y *= corr; o4[j].z *= corr; o4[j].w *= corr;
            }
            m = wgt;
        }
        float p = __expf(wgt - m);
        l += p;
        const float4* vrow = (const float4*)(Vsh + s * 32);
        #pragma unroll
        for (int j = 0; j < 8; j++) {
            float4 vv = vrow[j];
            o4[j].x += p * vv.x; o4[j].y += p * vv.y;
            o4[j].z += p * vv.z; o4[j].w += p * vv.w;
        }
    }
    __syncthreads();

    float* mlbuf = Ksh;
    float* obuf  = Ksh + 512;
    float* Lbuf  = Ksh + 512 + 8192;

    mlbuf[(qidx * 4 + ss) * 2 + 0] = m;
    mlbuf[(qidx * 4 + ss) * 2 + 1] = l;
    __syncthreads();

    float M = 0.f;
    #pragma unroll
    for (int i = 0; i < 4; i++) M = fmaxf(M, mlbuf[(qidx * 4 + i) * 2]);
    float L = 0.f;
    #pragma unroll
    for (int i = 0; i < 4; i++)
        L += mlbuf[(qidx * 4 + i) * 2 + 1] * __expf(mlbuf[(qidx * 4 + i) * 2] - M);

    float myscale = __expf(m - M);
    float* od = obuf + (qidx * 4 + ss) * 32;
    #pragma unroll
    for (int j = 0; j < 8; j++) {
        od[j * 4 + 0] = o4[j].x * myscale;
        od[j * 4 + 1] = o4[j].y * myscale;
        od[j * 4 + 2] = o4[j].z * myscale;
        od[j * 4 + 3] = o4[j].w * myscale;
    }
    if (ss == 0) Lbuf[qidx] = L;
    __syncthreads();

    for (int e = tid; e < 64 * 32; e += 256) {
        int qi = e >> 5, c = e & 31;
        float sum = obuf[(qi * 4 + 0) * 32 + c] + obuf[(qi * 4 + 1) * 32 + c]
                  + obuf[(qi * 4 + 2) * 32 + c] + obuf[(qi * 4 + 3) * 32 + c];
        float outv = __fdividef(sum, Lbuf[qi]);
        size_t idx = ((size_t)b * T + (t0 + qi)) * DM + hh * HC + c;
        x1[idx] = x[idx] + outv;
    }
}

// ---------------------------------------------------------------------------
extern "C" void kernel_launch(void* const* d_in, const int* in_sizes, int n_in,
                              void* d_out, int out_size)
{
    const float* x      = (const float*)d_in[0];
    const float* W_qkv  = (const float*)d_in[1];
    const float* b_qkv  = (const float*)d_in[2];
    const float* W_fc   = (const float*)d_in[3];
    const float* b_fc   = (const float*)d_in[4];
    const float* W_proj = (const float*)d_in[5];
    const float* b_proj = (const float*)d_in[6];
    float* out = (float*)d_out;

    float *p_qkv, *p_x1, *p_h;
    cudaGetSymbolAddress((void**)&p_qkv, g_qkv);
    cudaGetSymbolAddress((void**)&p_x1,  g_x1);
    cudaGetSymbolAddress((void**)&p_h,   g_h);

    // 1) qkv = x @ W_qkv + b_qkv            (1024 x 768, K=256)
    gemm_tc<0, false><<<dim3(12, 16), 256>>>(x, W_qkv, b_qkv, nullptr, p_qkv,
                                             NTOK, 3 * DM, DM);

    // 2) x1 = x + attention(qkv)
    cudaFuncSetAttribute(attn_kernel, cudaFuncAttributeMaxDynamicSharedMemorySize, 131072);
    attn_kernel<<<128, 256, 131072>>>(x, p_qkv, p_x1);

    // 3) h = quick_gelu(x1 @ W_fc + b_fc)   (1024 x 1024, K=256)
    gemm_tc<1, false><<<dim3(16, 16), 256>>>(p_x1, W_fc, b_fc, nullptr, p_h,
                                             NTOK, 4 * DM, DM);

    // 4) out = x1 + h @ W_proj + b_proj     (1024 x 256, K=1024)
    gemm_tc<0, true><<<dim3(4, 16), 256>>>(p_h, W_proj, b_proj, p_x1, out,
                                           NTOK, DM, 4 * DM);
}

// round 3
// speedup vs baseline: 2.0479x; 2.0479x over previous
#include <cuda_runtime.h>
#include <cuda_bf16.h>
#include <math.h>

// Shapes (fixed): B=2, T=512, D=256, H=8, c=32
#define NTOK 1024
#define DM   256
#define NH   8
#define HC   32
#define T    512

__device__ float g_qkv[NTOK * 3 * DM];
__device__ float g_x1 [NTOK * DM];
__device__ float g_h  [NTOK * 4 * DM];

__device__ __forceinline__ unsigned f2tf32(float f) {
    unsigned u;
    asm("cvt.rna.tf32.f32 %0, %1;" : "=r"(u) : "f"(f));
    return u;
}

__device__ __forceinline__ void cp16(void* smem_dst, const void* gsrc) {
    unsigned s = (unsigned)__cvta_generic_to_shared(smem_dst);
    asm volatile("cp.async.cg.shared.global [%0], [%1], 16;\n" :: "r"(s), "l"(gsrc));
}

// ---------------------------------------------------------------------------
// TF32 tensor-core GEMM, 2-stage cp.async pipeline.
// BM=64, BN=64, BK=32, 256 threads = 8 warps (2x4 warp grid, warp tile 32x16).
// As stride 36 floats (144B, 16B aligned), Bs stride 68 (272B, 16B aligned).
// ---------------------------------------------------------------------------
template<int ACT, bool RES>
__global__ void gemm_tc(const float* __restrict__ A, const float* __restrict__ B,
                        const float* __restrict__ bias, const float* __restrict__ res,
                        float* __restrict__ C, int M, int N, int K)
{
    __shared__ float As[2][64 * 36];
    __shared__ float Bs[2][32 * 68];

    const int tid  = threadIdx.x;
    const int w    = tid >> 5;
    const int lane = tid & 31;
    const int g    = lane >> 2;
    const int tg   = lane & 3;
    const int warpM = w >> 2;       // 0..1
    const int warpN = w & 3;        // 0..3

    const int row0 = blockIdx.y * 64;
    const int col0 = blockIdx.x * 64;

    float acc[2][2][4] = {};

    // chunk mapping: A 64x32 -> 512 x 16B chunks; B 32x64 -> 512 chunks
    auto load_tile = [&](int k0, int buf) {
        #pragma unroll
        for (int c = tid; c < 512; c += 256) {
            int rA = c >> 3, cA = (c & 7) * 4;
            cp16(&As[buf][rA * 36 + cA], A + (size_t)(row0 + rA) * K + k0 + cA);
            int rB = c >> 4, cB = (c & 15) * 4;
            cp16(&Bs[buf][rB * 68 + cB], B + (size_t)(k0 + rB) * N + col0 + cB);
        }
        asm volatile("cp.async.commit_group;\n");
    };

    const int nt = K >> 5;
    load_tile(0, 0);

    for (int i = 0; i < nt; i++) {
        if (i + 1 < nt) {
            load_tile((i + 1) << 5, (i + 1) & 1);
            asm volatile("cp.async.wait_group 1;\n");
        } else {
            asm volatile("cp.async.wait_group 0;\n");
        }
        __syncthreads();

        const float* Ab = As[i & 1];
        const float* Bb = Bs[i & 1];

        #pragma unroll
        for (int ks = 0; ks < 4; ks++) {
            const int kk = ks * 8;
            unsigned a[2][4], b[2][2];
            #pragma unroll
            for (int ii = 0; ii < 2; ii++) {
                const int rb = warpM * 32 + ii * 16;
                a[ii][0] = f2tf32(Ab[(rb + g    ) * 36 + kk + tg    ]);
                a[ii][1] = f2tf32(Ab[(rb + g + 8) * 36 + kk + tg    ]);
                a[ii][2] = f2tf32(Ab[(rb + g    ) * 36 + kk + tg + 4]);
                a[ii][3] = f2tf32(Ab[(rb + g + 8) * 36 + kk + tg + 4]);
            }
            #pragma unroll
            for (int j = 0; j < 2; j++) {
                const int cb = warpN * 16 + j * 8;
                b[j][0] = f2tf32(Bb[(kk + tg    ) * 68 + cb + g]);
                b[j][1] = f2tf32(Bb[(kk + tg + 4) * 68 + cb + g]);
            }
            #pragma unroll
            for (int ii = 0; ii < 2; ii++)
                #pragma unroll
                for (int j = 0; j < 2; j++) {
                    asm volatile(
                        "mma.sync.aligned.m16n8k8.row.col.f32.tf32.tf32.f32 "
                        "{%0,%1,%2,%3}, {%4,%5,%6,%7}, {%8,%9}, {%0,%1,%2,%3};"
                        : "+f"(acc[ii][j][0]), "+f"(acc[ii][j][1]),
                          "+f"(acc[ii][j][2]), "+f"(acc[ii][j][3])
                        : "r"(a[ii][0]), "r"(a[ii][1]), "r"(a[ii][2]), "r"(a[ii][3]),
                          "r"(b[j][0]), "r"(b[j][1]));
                }
        }
        __syncthreads();
    }

    // epilogue
    #pragma unroll
    for (int ii = 0; ii < 2; ii++) {
        const int rb = row0 + warpM * 32 + ii * 16;
        #pragma unroll
        for (int j = 0; j < 2; j++) {
            const int cb = col0 + warpN * 16 + j * 8;
            #pragma unroll
            for (int rg = 0; rg < 2; rg++) {
                const int r = rb + g + rg * 8;
                #pragma unroll
                for (int cg = 0; cg < 2; cg++) {
                    const int c = cb + tg * 2 + cg;
                    float v = acc[ii][j][rg * 2 + cg] + bias[c];
                    if (ACT == 1)
                        v = v * __fdividef(1.f, 1.f + __expf(-1.702f * v));
                    if (RES) v += res[(size_t)r * N + c];
                    C[(size_t)r * N + c] = v;
                }
            }
        }
    }
}

// ---------------------------------------------------------------------------
// L1-distance attention + residual (same algorithm as R1; proven correct)
// ---------------------------------------------------------------------------
__global__ void attn_kernel(const float* __restrict__ x, const float* __restrict__ qkv,
                            float* __restrict__ x1)
{
    extern __shared__ float sh[];
    float* Ksh = sh;
    float* Vsh = sh + 16384;

    const int bid = blockIdx.x;
    const int bh  = bid >> 3;
    const int qb  = bid & 7;
    const int b   = bh >> 3;
    const int hh  = bh & 7;
    const int tid = threadIdx.x;
    const int w   = tid >> 5;
    const int lane = tid & 31;
    const int t0  = qb * 64;

    const float* qkv_bh = qkv + (size_t)b * T * 768 + hh * 96;

    for (int i = tid; i < T * 8; i += 256) {
        int s = i >> 3, j = i & 7;
        ((float4*)Ksh)[i] = ((const float4*)(qkv_bh + (size_t)s * 768 + 32))[j];
        ((float4*)Vsh)[i] = ((const float4*)(qkv_bh + (size_t)s * 768 + 64))[j];
    }

    const int qg   = w & 1;
    const int ss   = w >> 1;
    const int qidx = qg * 32 + lane;
    const int t    = t0 + qidx;

    float4 q4[8];
    {
        const float4* qsrc = (const float4*)(qkv_bh + (size_t)t * 768);
        #pragma unroll
        for (int j = 0; j < 8; j++) q4[j] = qsrc[j];
    }
    __syncthreads();

    const float scale = 0.1767766952966369f;
    float m = 0.f, l = 0.f;
    float4 o4[8];
    #pragma unroll
    for (int j = 0; j < 8; j++) o4[j] = make_float4(0.f, 0.f, 0.f, 0.f);

    const int s_begin = ss * 128;
    for (int s = s_begin; s < s_begin + 128; s++) {
        const float4* krow = (const float4*)(Ksh + s * 32);
        float dist = 0.f;
        #pragma unroll
        for (int j = 0; j < 8; j++) {
            float4 kv = krow[j];
            dist += fabsf(q4[j].x - kv.x) + fabsf(q4[j].y - kv.y)
                  + fabsf(q4[j].z - kv.z) + fabsf(q4[j].w - kv.w);
        }
        float wgt = (s == t) ? 0.f : __fdividef(1.f, 0.001f + dist * scale);
        if (wgt > m) {
            float corr = __expf(m - wgt);
            l *= corr;
            #pragma unroll
            for (int j = 0; j < 8; j++) {
                o4[j].x *= corr; o4[j].y *= corr; o4[j].z *= corr; o4[j].w *= corr;
            }
            m = wgt;
        }
        float p = __expf(wgt - m);
        l += p;
        const float4* vrow = (const float4*)(Vsh + s * 32);
        #pragma unroll
        for (int j = 0; j < 8; j++) {
            float4 vv = vrow[j];
            o4[j].x += p * vv.x; o4[j].y += p * vv.y;
            o4[j].z += p * vv.z; o4[j].w += p * vv.w;
        }
    }
    __syncthreads();

    float* mlbuf = Ksh;
    float* obuf  = Ksh + 512;
    float* Lbuf  = Ksh + 512 + 8192;

    mlbuf[(qidx * 4 + ss) * 2 + 0] = m;
    mlbuf[(qidx * 4 + ss) * 2 + 1] = l;
    __syncthreads();

    float M = 0.f;
    #pragma unroll
    for (int i = 0; i < 4; i++) M = fmaxf(M, mlbuf[(qidx * 4 + i) * 2]);
    float L = 0.f;
    #pragma unroll
    for (int i = 0; i < 4; i++)
        L += mlbuf[(qidx * 4 + i) * 2 + 1] * __expf(mlbuf[(qidx * 4 + i) * 2] - M);

    float myscale = __expf(m - M);
    float* od = obuf + (qidx * 4 + ss) * 32;
    #pragma unroll
    for (int j = 0; j < 8; j++) {
        od[j * 4 + 0] = o4[j].x * myscale;
        od[j * 4 + 1] = o4[j].y * myscale;
        od[j * 4 + 2] = o4[j].z * myscale;
        od[j * 4 + 3] = o4[j].w * myscale;
    }
    if (ss == 0) Lbuf[qidx] = L;
    __syncthreads();

    for (int e = tid; e < 64 * 32; e += 256) {
        int qi = e >> 5, c = e & 31;
        float sum = obuf[(qi * 4 + 0) * 32 + c] + obuf[(qi * 4 + 1) * 32 + c]
                  + obuf[(qi * 4 + 2) * 32 + c] + obuf[(qi * 4 + 3) * 32 + c];
        float outv = __fdividef(sum, Lbuf[qi]);
        size_t idx = ((size_t)b * T + (t0 + qi)) * DM + hh * HC + c;
        x1[idx] = x[idx] + outv;
    }
}

// ---------------------------------------------------------------------------
extern "C" void kernel_launch(void* const* d_in, const int* in_sizes, int n_in,
                              void* d_out, int out_size)
{
    const float* x      = (const float*)d_in[0];
    const float* W_qkv  = (const float*)d_in[1];
    const float* b_qkv  = (const float*)d_in[2];
    const float* W_fc   = (const float*)d_in[3];
    const float* b_fc   = (const float*)d_in[4];
    const float* W_proj = (const float*)d_in[5];
    const float* b_proj = (const float*)d_in[6];
    float* out = (float*)d_out;

    float *p_qkv, *p_x1, *p_h;
    cudaGetSymbolAddress((void**)&p_qkv, g_qkv);
    cudaGetSymbolAddress((void**)&p_x1,  g_x1);
    cudaGetSymbolAddress((void**)&p_h,   g_h);

    // 1) qkv = x @ W_qkv + b_qkv            (1024 x 768, K=256) grid 12x16
    gemm_tc<0, false><<<dim3(12, 16), 256>>>(x, W_qkv, b_qkv, nullptr, p_qkv,
                                             NTOK, 3 * DM, DM);

    // 2) x1 = x + attention(qkv)
    cudaFuncSetAttribute(attn_kernel, cudaFuncAttributeMaxDynamicSharedMemorySize, 131072);
    attn_kernel<<<128, 256, 131072>>>(x, p_qkv, p_x1);

    // 3) h = quick_gelu(x1 @ W_fc + b_fc)   (1024 x 1024, K=256) grid 16x16
    gemm_tc<1, false><<<dim3(16, 16), 256>>>(p_x1, W_fc, b_fc, nullptr, p_h,
                                             NTOK, 4 * DM, DM);

    // 4) out = x1 + h @ W_proj + b_proj     (1024 x 256, K=1024) grid 4x16
    gemm_tc<0, true><<<dim3(4, 16), 256>>>(p_h, W_proj, b_proj, p_x1, out,
                                           NTOK, DM, 4 * DM);
}

// round 4
// speedup vs baseline: 2.1032x; 1.0270x over previous
#include <cuda_runtime.h>
#include <cuda_bf16.h>
#include <math.h>

// Shapes (fixed): B=2, T=512, D=256, H=8, c=32
#define NTOK 1024
#define DM   256
#define NH   8
#define HC   32
#define T    512

__device__ float g_qkv [NTOK * 3 * DM];       // 1024 x 768
__device__ float g_x1  [NTOK * DM];           // 1024 x 256
__device__ float g_h   [NTOK * 4 * DM];       // 1024 x 1024
__device__ float g_part[4 * NTOK * DM];       // 4 x (1024 x 256) split-K partials

__device__ __forceinline__ unsigned f2tf32(float f) {
    unsigned u;
    asm("cvt.rna.tf32.f32 %0, %1;" : "=r"(u) : "f"(f));
    return u;
}

__device__ __forceinline__ void cp16(void* smem_dst, const void* gsrc) {
    unsigned s = (unsigned)__cvta_generic_to_shared(smem_dst);
    asm volatile("cp.async.cg.shared.global [%0], [%1], 16;\n" :: "r"(s), "l"(gsrc));
}

// ---------------------------------------------------------------------------
// TF32 tensor-core GEMM, 3-stage cp.async pipeline.
// BM=64, BN=64, BK=32, 256 threads = 8 warps (2x4 warp grid, warp tile 32x16).
// RAW=true: write bare accumulators (split-K partial), ignore bias/act/res.
// A is (rows x lda), k-window [0, Klen) relative to the passed A/B pointers.
// ---------------------------------------------------------------------------
template<int ACT, bool RES, bool RAW>
__global__ void gemm_tc(const float* __restrict__ A, const float* __restrict__ B,
                        const float* __restrict__ bias, const float* __restrict__ res,
                        float* __restrict__ C, int M, int N, int Klen, int lda)
{
    __shared__ float As[3][64 * 36];
    __shared__ float Bs[3][32 * 68];

    const int tid  = threadIdx.x;
    const int w    = tid >> 5;
    const int lane = tid & 31;
    const int g    = lane >> 2;
    const int tg   = lane & 3;
    const int warpM = w >> 2;
    const int warpN = w & 3;

    const int row0 = blockIdx.y * 64;
    const int col0 = blockIdx.x * 64;

    float acc[2][2][4] = {};

    auto load_tile = [&](int k0, int buf) {
        #pragma unroll
        for (int c = tid; c < 512; c += 256) {
            int rA = c >> 3, cA = (c & 7) * 4;
            cp16(&As[buf][rA * 36 + cA], A + (size_t)(row0 + rA) * lda + k0 + cA);
            int rB = c >> 4, cB = (c & 15) * 4;
            cp16(&Bs[buf][rB * 68 + cB], B + (size_t)(k0 + rB) * N + col0 + cB);
        }
        asm volatile("cp.async.commit_group;\n");
    };

    const int nt = Klen >> 5;
    load_tile(0, 0);
    if (nt > 1) load_tile(32, 1);

    for (int i = 0; i < nt; i++) {
        if (i + 2 < nt) {
            load_tile((i + 2) << 5, (i + 2) % 3);
            asm volatile("cp.async.wait_group 2;\n");
        } else if (i + 1 < nt) {
            asm volatile("cp.async.wait_group 1;\n");
        } else {
            asm volatile("cp.async.wait_group 0;\n");
        }
        __syncthreads();

        const float* Ab = As[i % 3];
        const float* Bb = Bs[i % 3];

        #pragma unroll
        for (int ks = 0; ks < 4; ks++) {
            const int kk = ks * 8;
            unsigned a[2][4], b[2][2];
            #pragma unroll
            for (int ii = 0; ii < 2; ii++) {
                const int rb = warpM * 32 + ii * 16;
                a[ii][0] = f2tf32(Ab[(rb + g    ) * 36 + kk + tg    ]);
                a[ii][1] = f2tf32(Ab[(rb + g + 8) * 36 + kk + tg    ]);
                a[ii][2] = f2tf32(Ab[(rb + g    ) * 36 + kk + tg + 4]);
                a[ii][3] = f2tf32(Ab[(rb + g + 8) * 36 + kk + tg + 4]);
            }
            #pragma unroll
            for (int j = 0; j < 2; j++) {
                const int cb = warpN * 16 + j * 8;
                b[j][0] = f2tf32(Bb[(kk + tg    ) * 68 + cb + g]);
                b[j][1] = f2tf32(Bb[(kk + tg + 4) * 68 + cb + g]);
            }
            #pragma unroll
            for (int ii = 0; ii < 2; ii++)
                #pragma unroll
                for (int j = 0; j < 2; j++) {
                    asm volatile(
                        "mma.sync.aligned.m16n8k8.row.col.f32.tf32.tf32.f32 "
                        "{%0,%1,%2,%3}, {%4,%5,%6,%7}, {%8,%9}, {%0,%1,%2,%3};"
                        : "+f"(acc[ii][j][0]), "+f"(acc[ii][j][1]),
                          "+f"(acc[ii][j][2]), "+f"(acc[ii][j][3])
                        : "r"(a[ii][0]), "r"(a[ii][1]), "r"(a[ii][2]), "r"(a[ii][3]),
                          "r"(b[j][0]), "r"(b[j][1]));
                }
        }
        __syncthreads();
    }

    #pragma unroll
    for (int ii = 0; ii < 2; ii++) {
        const int rb = row0 + warpM * 32 + ii * 16;
        #pragma unroll
        for (int j = 0; j < 2; j++) {
            const int cb = col0 + warpN * 16 + j * 8;
            #pragma unroll
            for (int rg = 0; rg < 2; rg++) {
                const int r = rb + g + rg * 8;
                #pragma unroll
                for (int cg = 0; cg < 2; cg++) {
                    const int c = cb + tg * 2 + cg;
                    float v = acc[ii][j][rg * 2 + cg];
                    if (!RAW) {
                        v += bias[c];
                        if (ACT == 1)
                            v = v * __fdividef(1.f, 1.f + __expf(-1.702f * v));
                        if (RES) v += res[(size_t)r * N + c];
                    }
                    C[(size_t)r * N + c] = v;
                }
            }
        }
    }
}

// Split-K reduce for proj: out = sum_4(part) + bias + res, float4 vectorized.
__global__ void reduce_proj(const float* __restrict__ part, const float* __restrict__ bias,
                            const float* __restrict__ res, float* __restrict__ out)
{
    const int i = blockIdx.x * 256 + threadIdx.x;      // 65536 float4 total
    const float4* p = (const float4*)part;
    float4 s0 = p[i];
    float4 s1 = p[i + 65536];
    float4 s2 = p[i + 131072];
    float4 s3 = p[i + 196608];
    float4 bv = ((const float4*)bias)[i & 63];         // N=256 -> 64 float4/row
    float4 rv = ((const float4*)res)[i];
    float4 o;
    o.x = s0.x + s1.x + s2.x + s3.x + bv.x + rv.x;
    o.y = s0.y + s1.y + s2.y + s3.y + bv.y + rv.y;
    o.z = s0.z + s1.z + s2.z + s3.z + bv.z + rv.z;
    o.w = s0.w + s1.w + s2.w + s3.w + bv.w + rv.w;
    ((float4*)out)[i] = o;
}

// ---------------------------------------------------------------------------
// L1-distance attention + residual. 128 blocks x 512 threads (16 warps).
// Warp w: qg=w&1 (32-query group), ss=w>>1 (8 key-splits of 64 keys).
// K/V for (b,h) staged in 128KB smem; per-thread online softmax; 8-way merge.
// ---------------------------------------------------------------------------
__global__ void attn_kernel(const float* __restrict__ x, const float* __restrict__ qkv,
                            float* __restrict__ x1)
{
    extern __shared__ float sh[];
    float* Ksh = sh;            // 16384 floats
    float* Vsh = sh + 16384;    // 16384 floats

    const int bid = blockIdx.x;
    const int bh  = bid >> 3;
    const int qb  = bid & 7;
    const int b   = bh >> 3;
    const int hh  = bh & 7;
    const int tid = threadIdx.x;
    const int w   = tid >> 5;
    const int lane = tid & 31;
    const int t0  = qb * 64;

    const float* qkv_bh = qkv + (size_t)b * T * 768 + hh * 96;

    for (int i = tid; i < T * 8; i += 512) {
        int s = i >> 3, j = i & 7;
        ((float4*)Ksh)[i] = ((const float4*)(qkv_bh + (size_t)s * 768 + 32))[j];
        ((float4*)Vsh)[i] = ((const float4*)(qkv_bh + (size_t)s * 768 + 64))[j];
    }

    const int qg   = w & 1;
    const int ss   = w >> 1;             // 0..7
    const int qidx = qg * 32 + lane;     // 0..63
    const int t    = t0 + qidx;

    float4 q4[8];
    {
        const float4* qsrc = (const float4*)(qkv_bh + (size_t)t * 768);
        #pragma unroll
        for (int j = 0; j < 8; j++) q4[j] = qsrc[j];
    }
    __syncthreads();

    const float scale = 0.1767766952966369f;   // 1/sqrt(32)
    float m = 0.f, l = 0.f;
    float4 o4[8];
    #pragma unroll
    for (int j = 0; j < 8; j++) o4[j] = make_float4(0.f, 0.f, 0.f, 0.f);

    const int s_begin = ss * 64;
    for (int s = s_begin; s < s_begin + 64; s++) {
        const float4* krow = (const float4*)(Ksh + s * 32);   // warp-uniform
        float dist = 0.f;
        #pragma unroll
        for (int j = 0; j < 8; j++) {
            float4 kv = krow[j];
            dist += fabsf(q4[j].x - kv.x) + fabsf(q4[j].y - kv.y)
                  + fabsf(q4[j].z - kv.z) + fabsf(q4[j].w - kv.w);
        }
        float wgt = (s == t) ? 0.f : __fdividef(1.f, 0.001f + dist * scale);
        if (wgt > m) {
            float corr = __expf(m - wgt);
            l *= corr;
            #pragma unroll
            for (int j = 0; j < 8; j++) {
                o4[j].x *= corr; o4[j].y *= corr; o4[j].z *= corr; o4[j].w *= corr;
            }
            m = wgt;
        }
        float p = __expf(wgt - m);
        l += p;
        const float4* vrow = (const float4*)(Vsh + s * 32);   // warp-uniform
        #pragma unroll
        for (int j = 0; j < 8; j++) {
            float4 vv = vrow[j];
            o4[j].x += p * vv.x; o4[j].y += p * vv.y;
            o4[j].z += p * vv.z; o4[j].w += p * vv.w;
        }
    }
    __syncthreads();    // everyone done with K/V smem

    // 8-way split merge (reuse staged regions)
    // obuf[ss][qidx][c], qidx-stride 33 -> conflict-free stores & loads
    float* obuf  = sh;                     // 8 * 64 * 33 = 16896 floats
    float* mlbuf = sh + 16896;             // [64][8][2] = 1024
    float* Lbuf  = sh + 16896 + 1024;      // [64]

    mlbuf[(qidx * 8 + ss) * 2 + 0] = m;
    mlbuf[(qidx * 8 + ss) * 2 + 1] = l;
    __syncthreads();

    float M = 0.f;
    #pragma unroll
    for (int i = 0; i < 8; i++) M = fmaxf(M, mlbuf[(qidx * 8 + i) * 2]);
    float L = 0.f;
    #pragma unroll
    for (int i = 0; i < 8; i++)
        L += mlbuf[(qidx * 8 + i) * 2 + 1] * __expf(mlbuf[(qidx * 8 + i) * 2] - M);

    float myscale = __expf(m - M);
    float* od = obuf + (ss * 64 + qidx) * 33;
    #pragma unroll
    for (int j = 0; j < 8; j++) {
        od[j * 4 + 0] = o4[j].x * myscale;
        od[j * 4 + 1] = o4[j].y * myscale;
        od[j * 4 + 2] = o4[j].z * myscale;
        od[j * 4 + 3] = o4[j].w * myscale;
    }
    if (ss == 0) Lbuf[qidx] = L;
    __syncthreads();

    for (int e = tid; e < 64 * 32; e += 512) {
        int qi = e >> 5, c = e & 31;
        float sum = 0.f;
        #pragma unroll
        for (int p = 0; p < 8; p++)
            sum += obuf[(p * 64 + qi) * 33 + c];
        float outv = __fdividef(sum, Lbuf[qi]);
        size_t idx = ((size_t)b * T + (t0 + qi)) * DM + hh * HC + c;
        x1[idx] = x[idx] + outv;
    }
}

// ---------------------------------------------------------------------------
extern "C" void kernel_launch(void* const* d_in, const int* in_sizes, int n_in,
                              void* d_out, int out_size)
{
    const float* x      = (const float*)d_in[0];
    const float* W_qkv  = (const float*)d_in[1];
    const float* b_qkv  = (const float*)d_in[2];
    const float* W_fc   = (const float*)d_in[3];
    const float* b_fc   = (const float*)d_in[4];
    const float* W_proj = (const float*)d_in[5];
    const float* b_proj = (const float*)d_in[6];
    float* out = (float*)d_out;

    float *p_qkv, *p_x1, *p_h, *p_part;
    cudaGetSymbolAddress((void**)&p_qkv,  g_qkv);
    cudaGetSymbolAddress((void**)&p_x1,   g_x1);
    cudaGetSymbolAddress((void**)&p_h,    g_h);
    cudaGetSymbolAddress((void**)&p_part, g_part);

    // 1) qkv = x @ W_qkv + b_qkv            (1024 x 768, K=256) grid 192
    gemm_tc<0, false, false><<<dim3(12, 16), 256>>>(x, W_qkv, b_qkv, nullptr, p_qkv,
                                                    NTOK, 3 * DM, DM, DM);

    // 2) x1 = x + attention(qkv)            128 blocks x 512 threads
    cudaFuncSetAttribute(attn_kernel, cudaFuncAttributeMaxDynamicSharedMemorySize, 131072);
    attn_kernel<<<128, 512, 131072>>>(x, p_qkv, p_x1);

    // 3) h = quick_gelu(x1 @ W_fc + b_fc)   (1024 x 1024, K=256) grid 256
    gemm_tc<1, false, false><<<dim3(16, 16), 256>>>(p_x1, W_fc, b_fc, nullptr, p_h,
                                                    NTOK, 4 * DM, DM, DM);

    // 4) proj split-K x4: partials          (1024 x 256, K=256 each) grid 256
    for (int z = 0; z < 4; z++) {
        gemm_tc<0, false, true><<<dim3(4, 16), 256>>>(
            p_h + z * 256, W_proj + (size_t)z * 256 * DM, nullptr, nullptr,
            p_part + (size_t)z * NTOK * DM, NTOK, DM, 256, 4 * DM);
    }

    // 5) out = sum(partials) + b_proj + x1
    reduce_proj<<<256, 256>>>(p_part, b_proj, p_x1, out);
}

// round 5
// speedup vs baseline: 2.4672x; 1.1731x over previous
#include <cuda_runtime.h>
#include <cuda_bf16.h>
#include <math.h>

// Shapes (fixed): B=2, T=512, D=256, H=8, c=32
#define NTOK 1024
#define DM   256
#define NH   8
#define HC   32
#define T    512

__device__ float g_qkv [NTOK * 3 * DM];       // 1024 x 768
__device__ float g_x1  [NTOK * DM];           // 1024 x 256
__device__ float g_h   [NTOK * 4 * DM];       // 1024 x 1024
__device__ float g_part[4 * NTOK * DM];       // split-K partials

__device__ __forceinline__ unsigned f2tf32(float f) {
    unsigned u;
    asm("cvt.rna.tf32.f32 %0, %1;" : "=r"(u) : "f"(f));
    return u;
}

__device__ __forceinline__ void cp16(void* smem_dst, const void* gsrc) {
    unsigned s = (unsigned)__cvta_generic_to_shared(smem_dst);
    asm volatile("cp.async.cg.shared.global [%0], [%1], 16;\n" :: "r"(s), "l"(gsrc));
}

// packed f32x2 helpers (sm_100+)
__device__ __forceinline__ unsigned long long addx2(unsigned long long a, unsigned long long b) {
    unsigned long long d;
    asm("add.rn.f32x2 %0, %1, %2;" : "=l"(d) : "l"(a), "l"(b));
    return d;
}
__device__ __forceinline__ unsigned long long fmax2(unsigned long long a, unsigned long long b,
                                                    unsigned long long c) {
    unsigned long long d;
    asm("fma.rn.f32x2 %0, %1, %2, %3;" : "=l"(d) : "l"(a), "l"(b), "l"(c));
    return d;
}
__device__ __forceinline__ unsigned long long mulx2(unsigned long long a, unsigned long long b) {
    unsigned long long d;
    asm("mul.rn.f32x2 %0, %1, %2;" : "=l"(d) : "l"(a), "l"(b));
    return d;
}
__device__ __forceinline__ unsigned long long pack2(float lo, float hi) {
    unsigned long long d;
    asm("mov.b64 %0, {%1, %2};" : "=l"(d) : "f"(lo), "f"(hi));
    return d;
}
__device__ __forceinline__ void unpack2(unsigned long long v, float& lo, float& hi) {
    asm("mov.b64 {%0, %1}, %2;" : "=f"(lo), "=f"(hi) : "l"(v));
}

// ---------------------------------------------------------------------------
// TF32 tensor-core GEMM, 3-stage cp.async pipeline, optional split-K via
// blockIdx.z (RAW=true writes bare partials at z*M*N).
// BM=64, BN=64, BK=32, 256 threads, warp tile 32x16.
// ---------------------------------------------------------------------------
template<int ACT, bool RES, bool RAW>
__global__ void gemm_tc(const float* __restrict__ A, const float* __restrict__ B,
                        const float* __restrict__ bias, const float* __restrict__ res,
                        float* __restrict__ C, int M, int N, int Klen, int lda)
{
    __shared__ float As[3][64 * 36];
    __shared__ float Bs[3][32 * 68];

    const int tid  = threadIdx.x;
    const int w    = tid >> 5;
    const int lane = tid & 31;
    const int g    = lane >> 2;
    const int tg   = lane & 3;
    const int warpM = w >> 2;
    const int warpN = w & 3;

    const int row0 = blockIdx.y * 64;
    const int col0 = blockIdx.x * 64;

    // split-K offset
    const int kz = blockIdx.z * Klen;
    A += kz;
    B += (size_t)kz * N;
    if (RAW) C += (size_t)blockIdx.z * M * N;

    float acc[2][2][4] = {};

    auto load_tile = [&](int k0, int buf) {
        #pragma unroll
        for (int c = tid; c < 512; c += 256) {
            int rA = c >> 3, cA = (c & 7) * 4;
            cp16(&As[buf][rA * 36 + cA], A + (size_t)(row0 + rA) * lda + k0 + cA);
            int rB = c >> 4, cB = (c & 15) * 4;
            cp16(&Bs[buf][rB * 68 + cB], B + (size_t)(k0 + rB) * N + col0 + cB);
        }
        asm volatile("cp.async.commit_group;\n");
    };

    const int nt = Klen >> 5;
    load_tile(0, 0);
    if (nt > 1) load_tile(32, 1);

    for (int i = 0; i < nt; i++) {
        if (i + 2 < nt) {
            load_tile((i + 2) << 5, (i + 2) % 3);
            asm volatile("cp.async.wait_group 2;\n");
        } else if (i + 1 < nt) {
            asm volatile("cp.async.wait_group 1;\n");
        } else {
            asm volatile("cp.async.wait_group 0;\n");
        }
        __syncthreads();

        const float* Ab = As[i % 3];
        const float* Bb = Bs[i % 3];

        #pragma unroll
        for (int ks = 0; ks < 4; ks++) {
            const int kk = ks * 8;
            unsigned a[2][4], b[2][2];
            #pragma unroll
            for (int ii = 0; ii < 2; ii++) {
                const int rb = warpM * 32 + ii * 16;
                a[ii][0] = f2tf32(Ab[(rb + g    ) * 36 + kk + tg    ]);
                a[ii][1] = f2tf32(Ab[(rb + g + 8) * 36 + kk + tg    ]);
                a[ii][2] = f2tf32(Ab[(rb + g    ) * 36 + kk + tg + 4]);
                a[ii][3] = f2tf32(Ab[(rb + g + 8) * 36 + kk + tg + 4]);
            }
            #pragma unroll
            for (int j = 0; j < 2; j++) {
                const int cb = warpN * 16 + j * 8;
                b[j][0] = f2tf32(Bb[(kk + tg    ) * 68 + cb + g]);
                b[j][1] = f2tf32(Bb[(kk + tg + 4) * 68 + cb + g]);
            }
            #pragma unroll
            for (int ii = 0; ii < 2; ii++)
                #pragma unroll
                for (int j = 0; j < 2; j++) {
                    asm volatile(
                        "mma.sync.aligned.m16n8k8.row.col.f32.tf32.tf32.f32 "
                        "{%0,%1,%2,%3}, {%4,%5,%6,%7}, {%8,%9}, {%0,%1,%2,%3};"
                        : "+f"(acc[ii][j][0]), "+f"(acc[ii][j][1]),
                          "+f"(acc[ii][j][2]), "+f"(acc[ii][j][3])
                        : "r"(a[ii][0]), "r"(a[ii][1]), "r"(a[ii][2]), "r"(a[ii][3]),
                          "r"(b[j][0]), "r"(b[j][1]));
                }
        }
        __syncthreads();
    }

    #pragma unroll
    for (int ii = 0; ii < 2; ii++) {
        const int rb = row0 + warpM * 32 + ii * 16;
        #pragma unroll
        for (int j = 0; j < 2; j++) {
            const int cb = col0 + warpN * 16 + j * 8;
            #pragma unroll
            for (int rg = 0; rg < 2; rg++) {
                const int r = rb + g + rg * 8;
                #pragma unroll
                for (int cg = 0; cg < 2; cg++) {
                    const int c = cb + tg * 2 + cg;
                    float v = acc[ii][j][rg * 2 + cg];
                    if (!RAW) {
                        v += bias[c];
                        if (ACT == 1)
                            v = v * __fdividef(1.f, 1.f + __expf(-1.702f * v));
                        if (RES) v += res[(size_t)r * N + c];
                    }
                    C[(size_t)r * N + c] = v;
                }
            }
        }
    }
}

// Split-K reduce for proj: out = sum_4(part) + bias + res.
__global__ void reduce_proj(const float* __restrict__ part, const float* __restrict__ bias,
                            const float* __restrict__ res, float* __restrict__ out)
{
    const int i = blockIdx.x * 256 + threadIdx.x;      // 65536 float4
    const float4* p = (const float4*)part;
    float4 s0 = p[i];
    float4 s1 = p[i + 65536];
    float4 s2 = p[i + 131072];
    float4 s3 = p[i + 196608];
    float4 bv = ((const float4*)bias)[i & 63];
    float4 rv = ((const float4*)res)[i];
    float4 o;
    o.x = s0.x + s1.x + s2.x + s3.x + bv.x + rv.x;
    o.y = s0.y + s1.y + s2.y + s3.y + bv.y + rv.y;
    o.z = s0.z + s1.z + s2.z + s3.z + bv.z + rv.z;
    o.w = s0.w + s1.w + s2.w + s3.w + bv.w + rv.w;
    ((float4*)out)[i] = o;
}

// ---------------------------------------------------------------------------
// L1-distance attention + residual, packed f32x2 math.
// 128 blocks x 512 threads (16 warps). Warp w: qg=w&1, ss=w>>1 (8 key-splits).
// Ksh holds NEGATED K so d = q + (-k) is one FADD2; |d| via 64-bit AND (alu).
// ---------------------------------------------------------------------------
__global__ void attn_kernel(const float* __restrict__ x, const float* __restrict__ qkv,
                            float* __restrict__ x1)
{
    extern __shared__ float sh[];
    float* Ksh = sh;            // 16384 floats (negated K)
    float* Vsh = sh + 16384;    // 16384 floats

    const int bid = blockIdx.x;
    const int bh  = bid >> 3;
    const int qb  = bid & 7;
    const int b   = bh >> 3;
    const int hh  = bh & 7;
    const int tid = threadIdx.x;
    const int w   = tid >> 5;
    const int lane = tid & 31;
    const int t0  = qb * 64;

    const float* qkv_bh = qkv + (size_t)b * T * 768 + hh * 96;

    for (int i = tid; i < T * 8; i += 512) {
        int s = i >> 3, j = i & 7;
        float4 kv = ((const float4*)(qkv_bh + (size_t)s * 768 + 32))[j];
        kv.x = -kv.x; kv.y = -kv.y; kv.z = -kv.z; kv.w = -kv.w;
        ((float4*)Ksh)[i] = kv;
        ((float4*)Vsh)[i] = ((const float4*)(qkv_bh + (size_t)s * 768 + 64))[j];
    }

    const int qg   = w & 1;
    const int ss   = w >> 1;             // 0..7
    const int qidx = qg * 32 + lane;     // 0..63
    const int t    = t0 + qidx;

    unsigned long long q2[16];
    {
        const ulonglong2* qsrc = (const ulonglong2*)(qkv_bh + (size_t)t * 768);
        #pragma unroll
        for (int j = 0; j < 8; j++) {
            ulonglong2 v = qsrc[j];
            q2[2 * j] = v.x; q2[2 * j + 1] = v.y;
        }
    }
    __syncthreads();

    const float scale = 0.1767766952966369f;   // 1/sqrt(32)
    const unsigned long long ABSM = 0x7FFFFFFF7FFFFFFFULL;
    float m = 0.f, l = 0.f;
    unsigned long long o2[16];
    #pragma unroll
    for (int j = 0; j < 16; j++) o2[j] = 0ULL;

    const int s_begin = ss * 64;
    for (int s = s_begin; s < s_begin + 64; s++) {
        const ulonglong2* krow = (const ulonglong2*)(Ksh + s * 32);   // warp-uniform
        unsigned long long accA = 0ULL, accB = 0ULL;
        #pragma unroll
        for (int j = 0; j < 8; j++) {
            ulonglong2 kk = krow[j];
            unsigned long long d0 = addx2(q2[2 * j],     kk.x) & ABSM;
            unsigned long long d1 = addx2(q2[2 * j + 1], kk.y) & ABSM;
            accA = addx2(accA, d0);
            accB = addx2(accB, d1);
        }
        float a0, a1, b0, b1;
        unpack2(accA, a0, a1);
        unpack2(accB, b0, b1);
        float dist = (a0 + a1) + (b0 + b1);
        float wgt = (s == t) ? 0.f : __fdividef(1.f, 0.001f + dist * scale);
        if (wgt > m) {
            float corr = __expf(m - wgt);
            unsigned long long c2 = pack2(corr, corr);
            l *= corr;
            #pragma unroll
            for (int j = 0; j < 16; j++) o2[j] = mulx2(o2[j], c2);
            m = wgt;
        }
        float p = __expf(wgt - m);
        l += p;
        unsigned long long pp = pack2(p, p);
        const ulonglong2* vrow = (const ulonglong2*)(Vsh + s * 32);   // warp-uniform
        #pragma unroll
        for (int j = 0; j < 8; j++) {
            ulonglong2 vv = vrow[j];
            o2[2 * j]     = fmax2(pp, vv.x, o2[2 * j]);
            o2[2 * j + 1] = fmax2(pp, vv.y, o2[2 * j + 1]);
        }
    }
    __syncthreads();    // done with K/V smem

    // 8-way split merge. obuf[ss][qidx][c], qidx-stride 34 floats (u64 aligned).
    unsigned long long* obuf64 = (unsigned long long*)sh;   // 8*64*17 u64 = 17408 fl
    float* obuf  = sh;
    float* mlbuf = sh + 17408;             // [64][8][2] = 1024
    float* Lbuf  = sh + 17408 + 1024;      // [64]

    mlbuf[(qidx * 8 + ss) * 2 + 0] = m;
    mlbuf[(qidx * 8 + ss) * 2 + 1] = l;
    __syncthreads();

    float M = 0.f;
    #pragma unroll
    for (int i = 0; i < 8; i++) M = fmaxf(M, mlbuf[(qidx * 8 + i) * 2]);
    float L = 0.f;
    #pragma unroll
    for (int i = 0; i < 8; i++)
        L += mlbuf[(qidx * 8 + i) * 2 + 1] * __expf(mlbuf[(qidx * 8 + i) * 2] - M);

    float msc = __expf(m - M);
    unsigned long long ms2 = pack2(msc, msc);
    unsigned long long* od = obuf64 + (ss * 64 + qidx) * 17;
    #pragma unroll
    for (int j = 0; j < 16; j++) od[j] = mulx2(o2[j], ms2);
    if (ss == 0) Lbuf[qidx] = L;
    __syncthreads();

    for (int e = tid; e < 64 * 32; e += 512) {
        int qi = e >> 5, c = e & 31;
        float sum = 0.f;
        #pragma unroll
        for (int p = 0; p < 8; p++)
            sum += obuf[(p * 64 + qi) * 34 + c];
        float outv = __fdividef(sum, Lbuf[qi]);
        size_t idx = ((size_t)b * T + (t0 + qi)) * DM + hh * HC + c;
        x1[idx] = x[idx] + outv;
    }
}

// ---------------------------------------------------------------------------
extern "C" void kernel_launch(void* const* d_in, const int* in_sizes, int n_in,
                              void* d_out, int out_size)
{
    const float* x      = (const float*)d_in[0];
    const float* W_qkv  = (const float*)d_in[1];
    const float* b_qkv  = (const float*)d_in[2];
    const float* W_fc   = (const float*)d_in[3];
    const float* b_fc   = (const float*)d_in[4];
    const float* W_proj = (const float*)d_in[5];
    const float* b_proj = (const float*)d_in[6];
    float* out = (float*)d_out;

    float *p_qkv, *p_x1, *p_h, *p_part;
    cudaGetSymbolAddress((void**)&p_qkv,  g_qkv);
    cudaGetSymbolAddress((void**)&p_x1,   g_x1);
    cudaGetSymbolAddress((void**)&p_h,    g_h);
    cudaGetSymbolAddress((void**)&p_part, g_part);

    // 1) qkv = x @ W_qkv + b_qkv            (1024 x 768, K=256) grid 192
    gemm_tc<0, false, false><<<dim3(12, 16), 256>>>(x, W_qkv, b_qkv, nullptr, p_qkv,
                                                    NTOK, 3 * DM, DM, DM);

    // 2) x1 = x + attention(qkv)
    cudaFuncSetAttribute(attn_kernel, cudaFuncAttributeMaxDynamicSharedMemorySize, 131072);
    attn_kernel<<<128, 512, 131072>>>(x, p_qkv, p_x1);

    // 3) h = quick_gelu(x1 @ W_fc + b_fc)   (1024 x 1024, K=256) grid 256
    gemm_tc<1, false, false><<<dim3(16, 16), 256>>>(p_x1, W_fc, b_fc, nullptr, p_h,
                                                    NTOK, 4 * DM, DM, DM);

    // 4) proj split-K x4 in ONE launch      (1024 x 256, Ksplit=256) grid 256
    gemm_tc<0, false, true><<<dim3(4, 16, 4), 256>>>(p_h, W_proj, nullptr, nullptr,
                                                     p_part, NTOK, DM, 256, 4 * DM);

    // 5) out = sum(partials) + b_proj + x1
    reduce_proj<<<256, 256>>>(p_part, b_proj, p_x1, out);
}

// round 6
// speedup vs baseline: 2.5850x; 1.0477x over previous
#include <cuda_runtime.h>
#include <cuda_bf16.h>
#include <math.h>

// Shapes (fixed): B=2, T=512, D=256, H=8, c=32
#define NTOK 1024
#define DM   256
#define NH   8
#define HC   32
#define T    512
#define KSPLIT 8

__device__ float g_qkv [NTOK * 3 * DM];          // 1024 x 768
__device__ float g_x1  [NTOK * DM];              // 1024 x 256
__device__ float g_h   [NTOK * 4 * DM];          // 1024 x 1024
__device__ float g_part[KSPLIT * NTOK * DM];     // split-K partials

__device__ __forceinline__ void cp16(void* smem_dst, const void* gsrc) {
    unsigned s = (unsigned)__cvta_generic_to_shared(smem_dst);
    asm volatile("cp.async.cg.shared.global [%0], [%1], 16;\n" :: "r"(s), "l"(gsrc));
}

// packed f32x2 helpers (sm_100+)
__device__ __forceinline__ unsigned long long addx2(unsigned long long a, unsigned long long b) {
    unsigned long long d;
    asm("add.rn.f32x2 %0, %1, %2;" : "=l"(d) : "l"(a), "l"(b));
    return d;
}
__device__ __forceinline__ unsigned long long fmax2(unsigned long long a, unsigned long long b,
                                                    unsigned long long c) {
    unsigned long long d;
    asm("fma.rn.f32x2 %0, %1, %2, %3;" : "=l"(d) : "l"(a), "l"(b), "l"(c));
    return d;
}
__device__ __forceinline__ unsigned long long mulx2(unsigned long long a, unsigned long long b) {
    unsigned long long d;
    asm("mul.rn.f32x2 %0, %1, %2;" : "=l"(d) : "l"(a), "l"(b));
    return d;
}
__device__ __forceinline__ unsigned long long pack2(float lo, float hi) {
    unsigned long long d;
    asm("mov.b64 %0, {%1, %2};" : "=l"(d) : "f"(lo), "f"(hi));
    return d;
}
__device__ __forceinline__ void unpack2(unsigned long long v, float& lo, float& hi) {
    asm("mov.b64 {%0, %1}, %2;" : "=f"(lo), "=f"(hi) : "l"(v));
}

// ---------------------------------------------------------------------------
// TF32 tensor-core GEMM, 3-stage cp.async pipeline, split-K via blockIdx.z.
// BM=64, BN=64, BK=32, 256 threads, warp tile 32x16.
// fp32 values are fed directly to mma.tf32 (HW mantissa truncation) — no
// per-read cvt in the mainloop.
// ---------------------------------------------------------------------------
template<int ACT, bool RES, bool RAW>
__global__ void gemm_tc(const float* __restrict__ A, const float* __restrict__ B,
                        const float* __restrict__ bias, const float* __restrict__ res,
                        float* __restrict__ C, int M, int N, int Klen, int lda)
{
    __shared__ float As[3][64 * 36];
    __shared__ float Bs[3][32 * 68];

    const int tid  = threadIdx.x;
    const int w    = tid >> 5;
    const int lane = tid & 31;
    const int g    = lane >> 2;
    const int tg   = lane & 3;
    const int warpM = w >> 2;
    const int warpN = w & 3;

    const int row0 = blockIdx.y * 64;
    const int col0 = blockIdx.x * 64;

    const int kz = blockIdx.z * Klen;
    A += kz;
    B += (size_t)kz * N;
    if (RAW) C += (size_t)blockIdx.z * M * N;

    float acc[2][2][4] = {};

    auto load_tile = [&](int k0, int buf) {
        #pragma unroll
        for (int c = tid; c < 512; c += 256) {
            int rA = c >> 3, cA = (c & 7) * 4;
            cp16(&As[buf][rA * 36 + cA], A + (size_t)(row0 + rA) * lda + k0 + cA);
            int rB = c >> 4, cB = (c & 15) * 4;
            cp16(&Bs[buf][rB * 68 + cB], B + (size_t)(k0 + rB) * N + col0 + cB);
        }
        asm volatile("cp.async.commit_group;\n");
    };

    const int nt = Klen >> 5;
    load_tile(0, 0);
    if (nt > 1) load_tile(32, 1);

    for (int i = 0; i < nt; i++) {
        if (i + 2 < nt) {
            load_tile((i + 2) << 5, (i + 2) % 3);
            asm volatile("cp.async.wait_group 2;\n");
        } else if (i + 1 < nt) {
            asm volatile("cp.async.wait_group 1;\n");
        } else {
            asm volatile("cp.async.wait_group 0;\n");
        }
        __syncthreads();

        const float* Ab = As[i % 3];
        const float* Bb = Bs[i % 3];

        #pragma unroll
        for (int ks = 0; ks < 4; ks++) {
            const int kk = ks * 8;
            unsigned a[2][4], b[2][2];
            #pragma unroll
            for (int ii = 0; ii < 2; ii++) {
                const int rb = warpM * 32 + ii * 16;
                a[ii][0] = __float_as_uint(Ab[(rb + g    ) * 36 + kk + tg    ]);
                a[ii][1] = __float_as_uint(Ab[(rb + g + 8) * 36 + kk + tg    ]);
                a[ii][2] = __float_as_uint(Ab[(rb + g    ) * 36 + kk + tg + 4]);
                a[ii][3] = __float_as_uint(Ab[(rb + g + 8) * 36 + kk + tg + 4]);
            }
            #pragma unroll
            for (int j = 0; j < 2; j++) {
                const int cb = warpN * 16 + j * 8;
                b[j][0] = __float_as_uint(Bb[(kk + tg    ) * 68 + cb + g]);
                b[j][1] = __float_as_uint(Bb[(kk + tg + 4) * 68 + cb + g]);
            }
            #pragma unroll
            for (int ii = 0; ii < 2; ii++)
                #pragma unroll
                for (int j = 0; j < 2; j++) {
                    asm volatile(
                        "mma.sync.aligned.m16n8k8.row.col.f32.tf32.tf32.f32 "
                        "{%0,%1,%2,%3}, {%4,%5,%6,%7}, {%8,%9}, {%0,%1,%2,%3};"
                        : "+f"(acc[ii][j][0]), "+f"(acc[ii][j][1]),
                          "+f"(acc[ii][j][2]), "+f"(acc[ii][j][3])
                        : "r"(a[ii][0]), "r"(a[ii][1]), "r"(a[ii][2]), "r"(a[ii][3]),
                          "r"(b[j][0]), "r"(b[j][1]));
                }
        }
        __syncthreads();
    }

    #pragma unroll
    for (int ii = 0; ii < 2; ii++) {
        const int rb = row0 + warpM * 32 + ii * 16;
        #pragma unroll
        for (int j = 0; j < 2; j++) {
            const int cb = col0 + warpN * 16 + j * 8;
            #pragma unroll
            for (int rg = 0; rg < 2; rg++) {
                const int r = rb + g + rg * 8;
                const int c = cb + tg * 2;
                float v0 = acc[ii][j][rg * 2 + 0];
                float v1 = acc[ii][j][rg * 2 + 1];
                if (!RAW) {
                    v0 += bias[c];
                    v1 += bias[c + 1];
                    if (ACT == 1) {
                        v0 = v0 * __fdividef(1.f, 1.f + __expf(-1.702f * v0));
                        v1 = v1 * __fdividef(1.f, 1.f + __expf(-1.702f * v1));
                    }
                    if (RES) {
                        float2 rv = *(const float2*)&res[(size_t)r * N + c];
                        v0 += rv.x; v1 += rv.y;
                    }
                }
                float2 o; o.x = v0; o.y = v1;
                *(float2*)&C[(size_t)r * N + c] = o;
            }
        }
    }
}

// Split-K reduce for proj: out = sum_8(part) + bias + res.
__global__ void reduce_proj(const float* __restrict__ part, const float* __restrict__ bias,
                            const float* __restrict__ res, float* __restrict__ out)
{
    const int i = blockIdx.x * 256 + threadIdx.x;      // 65536 float4
    const float4* p = (const float4*)part;
    float4 bv = ((const float4*)bias)[i & 63];
    float4 rv = ((const float4*)res)[i];
    float sx = bv.x + rv.x, sy = bv.y + rv.y, sz = bv.z + rv.z, sw = bv.w + rv.w;
    #pragma unroll
    for (int z = 0; z < KSPLIT; z++) {
        float4 s = p[i + z * 65536];
        sx += s.x; sy += s.y; sz += s.z; sw += s.w;
    }
    float4 o; o.x = sx; o.y = sy; o.z = sz; o.w = sw;
    ((float4*)out)[i] = o;
}

// ---------------------------------------------------------------------------
// L1-distance attention + residual, packed f32x2 math.
// 128 blocks x 512 threads (16 warps). Warp w: qg=w&1, ss=w>>1 (8 key-splits).
// Ksh holds NEGATED K so d = q + (-k) is one FADD2; |d| via 64-bit AND (alu).
// ---------------------------------------------------------------------------
__global__ void attn_kernel(const float* __restrict__ x, const float* __restrict__ qkv,
                            float* __restrict__ x1)
{
    extern __shared__ float sh[];
    float* Ksh = sh;
    float* Vsh = sh + 16384;

    const int bid = blockIdx.x;
    const int bh  = bid >> 3;
    const int qb  = bid & 7;
    const int b   = bh >> 3;
    const int hh  = bh & 7;
    const int tid = threadIdx.x;
    const int w   = tid >> 5;
    const int lane = tid & 31;
    const int t0  = qb * 64;

    const float* qkv_bh = qkv + (size_t)b * T * 768 + hh * 96;

    for (int i = tid; i < T * 8; i += 512) {
        int s = i >> 3, j = i & 7;
        float4 kv = ((const float4*)(qkv_bh + (size_t)s * 768 + 32))[j];
        kv.x = -kv.x; kv.y = -kv.y; kv.z = -kv.z; kv.w = -kv.w;
        ((float4*)Ksh)[i] = kv;
        ((float4*)Vsh)[i] = ((const float4*)(qkv_bh + (size_t)s * 768 + 64))[j];
    }

    const int qg   = w & 1;
    const int ss   = w >> 1;
    const int qidx = qg * 32 + lane;
    const int t    = t0 + qidx;

    unsigned long long q2[16];
    {
        const ulonglong2* qsrc = (const ulonglong2*)(qkv_bh + (size_t)t * 768);
        #pragma unroll
        for (int j = 0; j < 8; j++) {
            ulonglong2 v = qsrc[j];
            q2[2 * j] = v.x; q2[2 * j + 1] = v.y;
        }
    }
    __syncthreads();

    const float scale = 0.1767766952966369f;
    const unsigned long long ABSM = 0x7FFFFFFF7FFFFFFFULL;
    float m = 0.f, l = 0.f;
    unsigned long long o2[16];
    #pragma unroll
    for (int j = 0; j < 16; j++) o2[j] = 0ULL;

    const int s_begin = ss * 64;
    for (int s = s_begin; s < s_begin + 64; s++) {
        const ulonglong2* krow = (const ulonglong2*)(Ksh + s * 32);
        unsigned long long accA = 0ULL, accB = 0ULL;
        #pragma unroll
        for (int j = 0; j < 8; j++) {
            ulonglong2 kk = krow[j];
            unsigned long long d0 = addx2(q2[2 * j],     kk.x) & ABSM;
            unsigned long long d1 = addx2(q2[2 * j + 1], kk.y) & ABSM;
            accA = addx2(accA, d0);
            accB = addx2(accB, d1);
        }
        float a0, a1, b0, b1;
        unpack2(accA, a0, a1);
        unpack2(accB, b0, b1);
        float dist = (a0 + a1) + (b0 + b1);
        float wgt = (s == t) ? 0.f : __fdividef(1.f, 0.001f + dist * scale);
        if (wgt > m) {
            float corr = __expf(m - wgt);
            unsigned long long c2 = pack2(corr, corr);
            l *= corr;
            #pragma unroll
            for (int j = 0; j < 16; j++) o2[j] = mulx2(o2[j], c2);
            m = wgt;
        }
        float p = __expf(wgt - m);
        l += p;
        unsigned long long pp = pack2(p, p);
        const ulonglong2* vrow = (const ulonglong2*)(Vsh + s * 32);
        #pragma unroll
        for (int j = 0; j < 8; j++) {
            ulonglong2 vv = vrow[j];
            o2[2 * j]     = fmax2(pp, vv.x, o2[2 * j]);
            o2[2 * j + 1] = fmax2(pp, vv.y, o2[2 * j + 1]);
        }
    }
    __syncthreads();

    unsigned long long* obuf64 = (unsigned long long*)sh;   // [8][64][17] u64
    float* obuf  = sh;
    float* mlbuf = sh + 17408;
    float* Lbuf  = sh + 17408 + 1024;

    mlbuf[(qidx * 8 + ss) * 2 + 0] = m;
    mlbuf[(qidx * 8 + ss) * 2 + 1] = l;
    __syncthreads();

    float M = 0.f;
    #pragma unroll
    for (int i = 0; i < 8; i++) M = fmaxf(M, mlbuf[(qidx * 8 + i) * 2]);
    float L = 0.f;
    #pragma unroll
    for (int i = 0; i < 8; i++)
        L += mlbuf[(qidx * 8 + i) * 2 + 1] * __expf(mlbuf[(qidx * 8 + i) * 2] - M);

    float msc = __expf(m - M);
    unsigned long long ms2 = pack2(msc, msc);
    unsigned long long* od = obuf64 + (ss * 64 + qidx) * 17;
    #pragma unroll
    for (int j = 0; j < 16; j++) od[j] = mulx2(o2[j], ms2);
    if (ss == 0) Lbuf[qidx] = L;
    __syncthreads();

    for (int e = tid; e < 64 * 32; e += 512) {
        int qi = e >> 5, c = e & 31;
        float sum = 0.f;
        #pragma unroll
        for (int p = 0; p < 8; p++)
            sum += obuf[(p * 64 + qi) * 34 + c];
        float outv = __fdividef(sum, Lbuf[qi]);
        size_t idx = ((size_t)b * T + (t0 + qi)) * DM + hh * HC + c;
        x1[idx] = x[idx] + outv;
    }
}

// ---------------------------------------------------------------------------
extern "C" void kernel_launch(void* const* d_in, const int* in_sizes, int n_in,
                              void* d_out, int out_size)
{
    const float* x      = (const float*)d_in[0];
    const float* W_qkv  = (const float*)d_in[1];
    const float* b_qkv  = (const float*)d_in[2];
    const float* W_fc   = (const float*)d_in[3];
    const float* b_fc   = (const float*)d_in[4];
    const float* W_proj = (const float*)d_in[5];
    const float* b_proj = (const float*)d_in[6];
    float* out = (float*)d_out;

    float *p_qkv, *p_x1, *p_h, *p_part;
    cudaGetSymbolAddress((void**)&p_qkv,  g_qkv);
    cudaGetSymbolAddress((void**)&p_x1,   g_x1);
    cudaGetSymbolAddress((void**)&p_h,    g_h);
    cudaGetSymbolAddress((void**)&p_part, g_part);

    // 1) qkv = x @ W_qkv + b_qkv            (1024 x 768, K=256) grid 192
    gemm_tc<0, false, false><<<dim3(12, 16), 256>>>(x, W_qkv, b_qkv, nullptr, p_qkv,
                                                    NTOK, 3 * DM, DM, DM);

    // 2) x1 = x + attention(qkv)
    cudaFuncSetAttribute(attn_kernel, cudaFuncAttributeMaxDynamicSharedMemorySize, 131072);
    attn_kernel<<<128, 512, 131072>>>(x, p_qkv, p_x1);

    // 3) h = quick_gelu(x1 @ W_fc + b_fc)   (1024 x 1024, K=256) grid 256
    gemm_tc<1, false, false><<<dim3(16, 16), 256>>>(p_x1, W_fc, b_fc, nullptr, p_h,
                                                    NTOK, 4 * DM, DM, DM);

    // 4) proj split-K x8 in ONE launch      (1024 x 256, Ksplit=128) grid 512
    gemm_tc<0, false, true><<<dim3(4, 16, KSPLIT), 256>>>(p_h, W_proj, nullptr, nullptr,
                                                          p_part, NTOK, DM, 1024 / KSPLIT,
                                                          4 * DM);

    // 5) out = sum(partials) + b_proj + x1
    reduce_proj<<<256, 256>>>(p_part, b_proj, p_x1, out);
}